// round 1
// baseline (speedup 1.0000x reference)
#include <cuda_runtime.h>
#include <math.h>

#define BB   4
#define SS   2048
#define HH   8
#define DHH  32
#define DIMM 256
#define NB   512          // SS / 4 compressed blocks
#define BS   (BB*SS)      // 8192 rows
#define BSD  (BS*DIMM)    // 2097152 floats

// ---------------- scratch (static device buffers; no allocs) ----------------
__device__ float g_h  [BSD];
__device__ float g_q  [BSD];
__device__ float g_k  [BSD];
__device__ float g_v  [BSD];
__device__ float g_o  [BSD];
__device__ float g_g  [BS*24];
__device__ float g_kc [BB*HH*DHH*NB];
__device__ float g_vc [BB*HH*DHH*NB];
__device__ float g_mid[BS*512];

// ---------------- LayerNorm: one warp per row of 256 ----------------
__global__ void ln_kernel(const float* __restrict__ x, const float* __restrict__ gw,
                          const float* __restrict__ bw, float* __restrict__ out)
{
    int warp = (blockIdx.x * blockDim.x + threadIdx.x) >> 5;
    int lane = threadIdx.x & 31;
    if (warp >= BS) return;
    const float* xr = x + (size_t)warp * DIMM;
    float vbuf[8];
    float s = 0.f;
    #pragma unroll
    for (int i = 0; i < 8; i++) { vbuf[i] = xr[lane + i*32]; s += vbuf[i]; }
    #pragma unroll
    for (int o = 16; o > 0; o >>= 1) s += __shfl_xor_sync(~0u, s, o);
    float m = s * (1.f/256.f);
    float sq = 0.f;
    #pragma unroll
    for (int i = 0; i < 8; i++) { float d = vbuf[i] - m; sq += d*d; }
    #pragma unroll
    for (int o = 16; o > 0; o >>= 1) sq += __shfl_xor_sync(~0u, sq, o);
    float rstd = rsqrtf(sq * (1.f/256.f) + 1e-5f);
    float* orow = out + (size_t)warp * DIMM;
    #pragma unroll
    for (int i = 0; i < 8; i++) {
        int c = lane + i*32;
        orow[c] = (vbuf[i] - m) * rstd * gw[c] + bw[c];
    }
}

// ---------------- generic tiled GEMM: C[M,N] = A[M,K] @ B[K,N] (+epilogue) ----------------
// EPI: 0=store  1=sigmoid  2=bias+leakyrelu  3=C+=val+bias  4=C+=val
template<int EPI>
__global__ void __launch_bounds__(256) gemm_kernel(
    const float* __restrict__ A, const float* __restrict__ B,
    const float* __restrict__ bias, float* __restrict__ C,
    int M, int N, int K)
{
    __shared__ float As[16][65];
    __shared__ float Bs[16][65];
    int tid = threadIdx.x;
    int tx = tid & 15, ty = tid >> 4;
    int bm = blockIdx.y << 6, bn = blockIdx.x << 6;
    float acc[4][4];
    #pragma unroll
    for (int i = 0; i < 4; i++)
        #pragma unroll
        for (int j = 0; j < 4; j++) acc[i][j] = 0.f;

    for (int k0 = 0; k0 < K; k0 += 16) {
        #pragma unroll
        for (int i = 0; i < 4; i++) {
            int e = tid + (i << 8);
            int r = e >> 4, kk = e & 15;
            As[kk][r] = A[(size_t)(bm + r)*K + k0 + kk];
        }
        #pragma unroll
        for (int i = 0; i < 4; i++) {
            int e = tid + (i << 8);
            int kk = e >> 6, c = e & 63;
            Bs[kk][c] = (bn + c < N) ? B[(size_t)(k0 + kk)*N + bn + c] : 0.f;
        }
        __syncthreads();
        #pragma unroll
        for (int kk = 0; kk < 16; kk++) {
            float a[4], bb[4];
            #pragma unroll
            for (int i = 0; i < 4; i++) a[i] = As[kk][(ty<<2)+i];
            #pragma unroll
            for (int j = 0; j < 4; j++) bb[j] = Bs[kk][(tx<<2)+j];
            #pragma unroll
            for (int i = 0; i < 4; i++)
                #pragma unroll
                for (int j = 0; j < 4; j++)
                    acc[i][j] = fmaf(a[i], bb[j], acc[i][j]);
        }
        __syncthreads();
    }
    #pragma unroll
    for (int i = 0; i < 4; i++) {
        int row = bm + (ty<<2) + i;
        #pragma unroll
        for (int j = 0; j < 4; j++) {
            int col = bn + (tx<<2) + j;
            if (col >= N) continue;
            size_t idx = (size_t)row * N + col;
            float val = acc[i][j];
            if (EPI == 0)      C[idx] = val;
            else if (EPI == 1) C[idx] = 1.f / (1.f + expf(-val));
            else if (EPI == 2) { float z = val + bias[col]; C[idx] = z > 0.f ? z : 0.01f*z; }
            else if (EPI == 3) C[idx] += val + bias[col];
            else if (EPI == 4) C[idx] += val;
        }
    }
}

// ---------------- KV mean-pool into transposed [B,H,DH,NB] layout ----------------
__global__ void pool_kernel(const float* __restrict__ k, const float* __restrict__ v,
                            float* __restrict__ kc, float* __restrict__ vc)
{
    int wid = (blockIdx.x * blockDim.x + threadIdx.x) >> 5;  // [0, B*H*NB)
    int lane = threadIdx.x & 31;
    if (wid >= BB*HH*NB) return;
    int n = wid % NB;
    int h = (wid / NB) % HH;
    int b = wid / (NB*HH);
    float sk = 0.f, sv = 0.f;
    #pragma unroll
    for (int c = 0; c < 4; c++) {
        size_t idx = ((size_t)(b*SS + n*4 + c)*HH + h)*DHH + lane;
        sk += k[idx]; sv += v[idx];
    }
    size_t oidx = ((size_t)(b*HH + h)*DHH + lane)*NB + n;
    kc[oidx] = sk * 0.25f;
    vc[oidx] = sv * 0.25f;
}

// ---------------- fused NSA attention: one warp per (b,h,t) ----------------
__global__ void __launch_bounds__(128) nsa_attn_kernel(
    const float* __restrict__ q, const float* __restrict__ k, const float* __restrict__ v,
    const float* __restrict__ kc, const float* __restrict__ vc,
    const float* __restrict__ g, float* __restrict__ o)
{
    int wid  = (blockIdx.x * 128 + threadIdx.x) >> 5;
    int lane = threadIdx.x & 31;
    int t = wid & (SS - 1);
    int h = (wid >> 11) & (HH - 1);
    int b = wid >> 14;

    const float SCALE = 0.17677669529663687f;  // 32^-0.5
    float qlane = q[((size_t)(b*SS + t)*HH + h)*DHH + lane] * SCALE;
    float qv[32];
    #pragma unroll
    for (int kk = 0; kk < 32; kk++) qv[kk] = __shfl_sync(~0u, qlane, kk);

    int own  = t >> 2;
    int nvis = (t + 1) >> 2;   // # blocks with blk_end <= t

    const float* kcb = kc + (size_t)(b*HH + h)*DHH*NB;
    const float* vcb = vc + (size_t)(b*HH + h)*DHH*NB;

    // ---- compressed branch (online softmax) + top-1 non-own visible block ----
    float oc = 0.f;
    float bval = -INFINITY; int bidx = NB;
    if (nvis > 0) {
        float Ml = -INFINITY, Z = 0.f;
        float av[32];
        #pragma unroll
        for (int j = 0; j < 32; j++) av[j] = 0.f;
        int ni = (nvis + 31) >> 5;
        for (int i = 0; i < ni; i++) {
            int n = lane + (i << 5);   // n < NB always; loads in-bounds
            float s = 0.f;
            #pragma unroll
            for (int kk = 0; kk < 32; kk++)
                s = fmaf(qv[kk], kcb[kk*NB + n], s);
            if (n < nvis) {
                if (n != own && s > bval) { bval = s; bidx = n; }
                if (s > Ml) {
                    float r = __expf(Ml - s);   // 0 when Ml = -inf
                    Z *= r;
                    #pragma unroll
                    for (int j = 0; j < 32; j++) av[j] *= r;
                    Ml = s;
                }
                float p = __expf(s - Ml);
                Z += p;
                #pragma unroll
                for (int j = 0; j < 32; j++)
                    av[j] = fmaf(p, vcb[j*NB + n], av[j]);
            }
        }
        // merge lanes: global max, rescale, reduce Z and av
        float Mg = Ml;
        #pragma unroll
        for (int off = 16; off > 0; off >>= 1)
            Mg = fmaxf(Mg, __shfl_xor_sync(~0u, Mg, off));
        float r = __expf(Ml - Mg);  // 0 for empty lanes
        Z *= r;
        #pragma unroll
        for (int j = 0; j < 32; j++) av[j] *= r;
        #pragma unroll
        for (int off = 16; off > 0; off >>= 1) Z += __shfl_xor_sync(~0u, Z, off);
        float accj = 0.f;
        #pragma unroll
        for (int j = 0; j < 32; j++) {
            float tv = av[j];
            #pragma unroll
            for (int off = 16; off > 0; off >>= 1) tv += __shfl_xor_sync(~0u, tv, off);
            if (j == lane) accj = tv;
        }
        oc = accj / Z;
        // top-1 reduce: max value, tie -> lowest index (matches lax.top_k)
        #pragma unroll
        for (int off = 16; off > 0; off >>= 1) {
            float ov = __shfl_xor_sync(~0u, bval, off);
            int   oi = __shfl_xor_sync(~0u, bidx, off);
            if (ov > bval || (ov == bval && oi < bidx)) { bval = ov; bidx = oi; }
        }
    }
    // no visible non-own block -> pc pattern is {own:-1, rest:0} -> first non-own index
    if (bval == -INFINITY) bidx = (own == 0) ? 1 : 0;

    // ---- selection branch: blocks {own, top1}, 8 keys, mask pos<=t ----
    int blks[2]; blks[0] = own; blks[1] = bidx;
    float sc8[8];
    float smax = -INFINITY;
    #pragma unroll
    for (int m = 0; m < 2; m++) {
        #pragma unroll
        for (int c = 0; c < 4; c++) {
            int pos = blks[m]*4 + c;
            float sp = qlane * k[((size_t)(b*SS + pos)*HH + h)*DHH + lane];
            #pragma unroll
            for (int off = 16; off > 0; off >>= 1) sp += __shfl_xor_sync(~0u, sp, off);
            float s = (pos <= t) ? sp : -INFINITY;
            sc8[m*4 + c] = s;
            smax = fmaxf(smax, s);
        }
    }
    float zf = 0.f, ofv = 0.f;
    #pragma unroll
    for (int e = 0; e < 8; e++) {
        int pos = blks[e >> 2]*4 + (e & 3);
        float p = __expf(sc8[e] - smax);
        zf += p;
        ofv = fmaf(p, v[((size_t)(b*SS + pos)*HH + h)*DHH + lane], ofv);
    }
    ofv /= zf;

    // ---- sliding window branch: keys {t-1, t} ----
    float s1 = qlane * k[((size_t)(b*SS + t)*HH + h)*DHH + lane];
    #pragma unroll
    for (int off = 16; off > 0; off >>= 1) s1 += __shfl_xor_sync(~0u, s1, off);
    int tp = (t > 0) ? t - 1 : 0;
    float s0 = qlane * k[((size_t)(b*SS + tp)*HH + h)*DHH + lane];
    #pragma unroll
    for (int off = 16; off > 0; off >>= 1) s0 += __shfl_xor_sync(~0u, s0, off);
    if (t == 0) s0 = -INFINITY;
    float wm = fmaxf(s0, s1);
    float p0 = __expf(s0 - wm), p1 = __expf(s1 - wm);
    float owv = fmaf(p0, v[((size_t)(b*SS + tp)*HH + h)*DHH + lane],
                     p1 * v[((size_t)(b*SS + t )*HH + h)*DHH + lane]) / (p0 + p1);

    // ---- gated combine ----
    const float* gr = g + (size_t)(b*SS + t)*24;
    float res = gr[h]*oc + gr[8 + h]*ofv + gr[16 + h]*owv;
    o[((size_t)(b*SS + t)*HH + h)*DHH + lane] = res;
}

// ---------------- host orchestration ----------------
extern "C" void kernel_launch(void* const* d_in, const int* in_sizes, int n_in,
                              void* d_out, int out_size)
{
    const float* x_in   = (const float*)d_in[0];
    const float* ln_a_g = (const float*)d_in[1];
    const float* ln_a_b = (const float*)d_in[2];
    const float* Wq     = (const float*)d_in[3];
    const float* Wk     = (const float*)d_in[4];
    const float* Wv     = (const float*)d_in[5];
    const float* Wg     = (const float*)d_in[6];
    const float* Wo     = (const float*)d_in[7];
    const float* ln_f_g = (const float*)d_in[8];
    const float* ln_f_b = (const float*)d_in[9];
    const float* W1     = (const float*)d_in[10];
    const float* b1     = (const float*)d_in[11];
    const float* W2     = (const float*)d_in[12];
    const float* b2     = (const float*)d_in[13];
    float* x = (float*)d_out;

    float *ph, *pq, *pk, *pv, *po, *pg, *pkc, *pvc, *pmid;
    cudaGetSymbolAddress((void**)&ph,   g_h);
    cudaGetSymbolAddress((void**)&pq,   g_q);
    cudaGetSymbolAddress((void**)&pk,   g_k);
    cudaGetSymbolAddress((void**)&pv,   g_v);
    cudaGetSymbolAddress((void**)&po,   g_o);
    cudaGetSymbolAddress((void**)&pg,   g_g);
    cudaGetSymbolAddress((void**)&pkc,  g_kc);
    cudaGetSymbolAddress((void**)&pvc,  g_vc);
    cudaGetSymbolAddress((void**)&pmid, g_mid);

    cudaMemcpyAsync(x, x_in, (size_t)BSD * sizeof(float), cudaMemcpyDeviceToDevice, 0);

    for (int l = 0; l < 2; l++) {
        for (int j2 = 0; j2 < 2; j2++) {
            int li = l*2 + j2;
            ln_kernel<<<BS/8, 256>>>(x, ln_a_g + li*DIMM, ln_a_b + li*DIMM, ph);
            gemm_kernel<0><<<dim3(4, BS/64), 256>>>(ph, Wq + (size_t)li*DIMM*DIMM, nullptr, pq, BS, DIMM, DIMM);
            gemm_kernel<0><<<dim3(4, BS/64), 256>>>(ph, Wk + (size_t)li*DIMM*DIMM, nullptr, pk, BS, DIMM, DIMM);
            gemm_kernel<0><<<dim3(4, BS/64), 256>>>(ph, Wv + (size_t)li*DIMM*DIMM, nullptr, pv, BS, DIMM, DIMM);
            gemm_kernel<1><<<dim3(1, BS/64), 256>>>(ph, Wg + (size_t)li*DIMM*24,   nullptr, pg, BS, 24,   DIMM);
            pool_kernel<<<(BB*HH*NB*32)/256, 256>>>(pk, pv, pkc, pvc);
            nsa_attn_kernel<<<(BB*HH*SS)/4, 128>>>(pq, pk, pv, pkc, pvc, pg, po);
            gemm_kernel<4><<<dim3(4, BS/64), 256>>>(po, Wo + (size_t)li*DIMM*DIMM, nullptr, x, BS, DIMM, DIMM);
        }
        ln_kernel<<<BS/8, 256>>>(x, ln_f_g + l*DIMM, ln_f_b + l*DIMM, ph);
        gemm_kernel<2><<<dim3(8, BS/64), 256>>>(ph,   W1 + (size_t)l*DIMM*512, b1 + l*512,  pmid, BS, 512,  DIMM);
        gemm_kernel<3><<<dim3(4, BS/64), 256>>>(pmid, W2 + (size_t)l*512*DIMM, b2 + l*DIMM, x,    BS, DIMM, 512);
    }
}

// round 2
// speedup vs baseline: 2.3120x; 2.3120x over previous
#include <cuda_runtime.h>
#include <math.h>

#define BB   4
#define SS   2048
#define HH   8
#define DHH  32
#define DIMM 256
#define NB   512          // SS / 4 compressed blocks
#define BS   (BB*SS)      // 8192 rows
#define BSD  (BS*DIMM)    // 2097152 floats
#define QT   256          // queries per attn block
#define NQT  (SS/QT)      // 8 qtiles

// ---------------- scratch (static device buffers; no allocs) ----------------
__device__ float g_h  [BSD];
__device__ float g_q  [BSD];
__device__ float g_k  [BSD];
__device__ float g_v  [BSD];
__device__ float g_o  [BSD];
__device__ float g_g  [BS*24];
__device__ float g_kc [BB*HH*DHH*NB];
__device__ float g_vc [BB*HH*DHH*NB];
__device__ float g_mid[BS*512];

// ---------------- LayerNorm: one warp per row of 256 ----------------
__global__ void ln_kernel(const float* __restrict__ x, const float* __restrict__ gw,
                          const float* __restrict__ bw, float* __restrict__ out)
{
    int warp = (blockIdx.x * blockDim.x + threadIdx.x) >> 5;
    int lane = threadIdx.x & 31;
    if (warp >= BS) return;
    const float* xr = x + (size_t)warp * DIMM;
    float vbuf[8];
    float s = 0.f;
    #pragma unroll
    for (int i = 0; i < 8; i++) { vbuf[i] = xr[lane + i*32]; s += vbuf[i]; }
    #pragma unroll
    for (int o = 16; o > 0; o >>= 1) s += __shfl_xor_sync(~0u, s, o);
    float m = s * (1.f/256.f);
    float sq = 0.f;
    #pragma unroll
    for (int i = 0; i < 8; i++) { float d = vbuf[i] - m; sq += d*d; }
    #pragma unroll
    for (int o = 16; o > 0; o >>= 1) sq += __shfl_xor_sync(~0u, sq, o);
    float rstd = rsqrtf(sq * (1.f/256.f) + 1e-5f);
    float* orow = out + (size_t)warp * DIMM;
    #pragma unroll
    for (int i = 0; i < 8; i++) {
        int c = lane + i*32;
        orow[c] = (vbuf[i] - m) * rstd * gw[c] + bw[c];
    }
}

// ---------------- small GEMM (kept for gate, N=24) ----------------
// EPI: 1=sigmoid
template<int EPI>
__global__ void __launch_bounds__(256) gemm_kernel(
    const float* __restrict__ A, const float* __restrict__ B,
    const float* __restrict__ bias, float* __restrict__ C,
    int M, int N, int K)
{
    __shared__ float As[16][65];
    __shared__ float Bs[16][65];
    int tid = threadIdx.x;
    int tx = tid & 15, ty = tid >> 4;
    int bm = blockIdx.y << 6, bn = blockIdx.x << 6;
    float acc[4][4];
    #pragma unroll
    for (int i = 0; i < 4; i++)
        #pragma unroll
        for (int j = 0; j < 4; j++) acc[i][j] = 0.f;

    for (int k0 = 0; k0 < K; k0 += 16) {
        #pragma unroll
        for (int i = 0; i < 4; i++) {
            int e = tid + (i << 8);
            int r = e >> 4, kk = e & 15;
            As[kk][r] = A[(size_t)(bm + r)*K + k0 + kk];
        }
        #pragma unroll
        for (int i = 0; i < 4; i++) {
            int e = tid + (i << 8);
            int kk = e >> 6, c = e & 63;
            Bs[kk][c] = (bn + c < N) ? B[(size_t)(k0 + kk)*N + bn + c] : 0.f;
        }
        __syncthreads();
        #pragma unroll
        for (int kk = 0; kk < 16; kk++) {
            float a[4], bb[4];
            #pragma unroll
            for (int i = 0; i < 4; i++) a[i] = As[kk][(ty<<2)+i];
            #pragma unroll
            for (int j = 0; j < 4; j++) bb[j] = Bs[kk][(tx<<2)+j];
            #pragma unroll
            for (int i = 0; i < 4; i++)
                #pragma unroll
                for (int j = 0; j < 4; j++)
                    acc[i][j] = fmaf(a[i], bb[j], acc[i][j]);
        }
        __syncthreads();
    }
    #pragma unroll
    for (int i = 0; i < 4; i++) {
        int row = bm + (ty<<2) + i;
        #pragma unroll
        for (int j = 0; j < 4; j++) {
            int col = bn + (tx<<2) + j;
            if (col >= N) continue;
            size_t idx = (size_t)row * N + col;
            float val = acc[i][j];
            if (EPI == 1) C[idx] = 1.f / (1.f + expf(-val));
            else          C[idx] = val;
        }
    }
}

// ---------------- big GEMM: 128x128 tile, BK=16, 8x8 micro ----------------
// requires M%128==0, N%128==0, K%16==0
// EPI: 0=store  2=bias+leakyrelu  3=C+=val+bias  4=C+=val
template<int EPI>
__global__ void __launch_bounds__(256) gemm128_kernel(
    const float* __restrict__ A, const float* __restrict__ B,
    const float* __restrict__ bias, float* __restrict__ C,
    int M, int N, int K)
{
    __shared__ float As[16][132];   // [kk][row], row pad keeps 16B alignment (132*4=528)
    __shared__ float Bs[16][128];
    int tid = threadIdx.x;
    int tx = tid & 15, ty = tid >> 4;
    int bm = blockIdx.y << 7, bn = blockIdx.x << 7;
    float acc[8][8];
    #pragma unroll
    for (int i = 0; i < 8; i++)
        #pragma unroll
        for (int j = 0; j < 8; j++) acc[i][j] = 0.f;

    for (int k0 = 0; k0 < K; k0 += 16) {
        #pragma unroll
        for (int i = 0; i < 2; i++) {
            int idx = tid + (i << 8);
            int r = idx >> 2, kq = idx & 3;
            float4 a4 = *(const float4*)(A + (size_t)(bm + r)*K + k0 + (kq << 2));
            As[(kq<<2)+0][r] = a4.x;
            As[(kq<<2)+1][r] = a4.y;
            As[(kq<<2)+2][r] = a4.z;
            As[(kq<<2)+3][r] = a4.w;
        }
        #pragma unroll
        for (int i = 0; i < 2; i++) {
            int idx = tid + (i << 8);
            int kk = idx >> 5, cq = idx & 31;
            *(float4*)(&Bs[kk][cq << 2]) =
                *(const float4*)(B + (size_t)(k0 + kk)*N + bn + (cq << 2));
        }
        __syncthreads();
        #pragma unroll
        for (int kk = 0; kk < 16; kk++) {
            float a[8], bb[8];
            #pragma unroll
            for (int i = 0; i < 8; i++) a[i]  = As[kk][(ty<<3) + i];
            #pragma unroll
            for (int j = 0; j < 8; j++) bb[j] = Bs[kk][(tx<<3) + j];
            #pragma unroll
            for (int i = 0; i < 8; i++)
                #pragma unroll
                for (int j = 0; j < 8; j++)
                    acc[i][j] = fmaf(a[i], bb[j], acc[i][j]);
        }
        __syncthreads();
    }
    #pragma unroll
    for (int i = 0; i < 8; i++) {
        int row = bm + (ty<<3) + i;
        #pragma unroll
        for (int j = 0; j < 8; j++) {
            int col = bn + (tx<<3) + j;
            size_t idx = (size_t)row * N + col;
            float val = acc[i][j];
            if (EPI == 0)      C[idx] = val;
            else if (EPI == 2) { float z = val + bias[col]; C[idx] = z > 0.f ? z : 0.01f*z; }
            else if (EPI == 3) C[idx] += val + bias[col];
            else if (EPI == 4) C[idx] += val;
        }
    }
}

// ---------------- KV mean-pool into transposed [B,H,DH,NB] layout ----------------
__global__ void pool_kernel(const float* __restrict__ k, const float* __restrict__ v,
                            float* __restrict__ kc, float* __restrict__ vc)
{
    int wid = (blockIdx.x * blockDim.x + threadIdx.x) >> 5;  // [0, B*H*NB)
    int lane = threadIdx.x & 31;
    if (wid >= BB*HH*NB) return;
    int n = wid % NB;
    int h = (wid / NB) % HH;
    int b = wid / (NB*HH);
    float sk = 0.f, sv = 0.f;
    #pragma unroll
    for (int c = 0; c < 4; c++) {
        size_t idx = ((size_t)(b*SS + n*4 + c)*HH + h)*DHH + lane;
        sk += k[idx]; sv += v[idx];
    }
    size_t oidx = ((size_t)(b*HH + h)*DHH + lane)*NB + n;
    kc[oidx] = sk * 0.25f;
    vc[oidx] = sv * 0.25f;
}

// ---------------- fused NSA attention: one THREAD per (b,h,t), tiled kc/vc in smem ----------------
__global__ void __launch_bounds__(256) nsa_attn_kernel(
    const float* __restrict__ q, const float* __restrict__ k, const float* __restrict__ v,
    const float* __restrict__ kc, const float* __restrict__ vc,
    const float* __restrict__ g, float* __restrict__ o)
{
    __shared__ float kcs[32][64];
    __shared__ float vcs[32][64];

    int tid   = threadIdx.x;
    int qtile = blockIdx.x & (NQT - 1);
    int h     = (blockIdx.x / NQT) & (HH - 1);
    int b     = blockIdx.x / (NQT * HH);
    int t     = qtile * QT + tid;

    const float SCALE = 0.17677669529663687f;  // 32^-0.5
    float qv[32];
    {
        const float4* qr = (const float4*)(q + ((size_t)(b*SS + t)*HH + h)*DHH);
        #pragma unroll
        for (int i = 0; i < 8; i++) {
            float4 f = qr[i];
            qv[4*i+0] = f.x * SCALE; qv[4*i+1] = f.y * SCALE;
            qv[4*i+2] = f.z * SCALE; qv[4*i+3] = f.w * SCALE;
        }
    }

    int own = t >> 2;
    const float* kcb = kc + (size_t)(b*HH + h)*DHH*NB;
    const float* vcb = vc + (size_t)(b*HH + h)*DHH*NB;

    float Ml = -INFINITY, Z = 0.f;
    float av[32];
    #pragma unroll
    for (int j = 0; j < 32; j++) av[j] = 0.f;
    float bval = -INFINITY; int bidx = NB;

    // tiles 0..qtile-1 are fully visible to every thread in this block;
    // tile==qtile is the partial tile (local lim = (tid+1)>>2, local own = tid>>2)
    for (int tile = 0; tile <= qtile; tile++) {
        int n0 = tile << 6;
        if (tile) __syncthreads();
        #pragma unroll
        for (int i = 0; i < 8; i++) {
            int idx = tid + (i << 8);
            int kk = idx >> 6, n = idx & 63;
            kcs[kk][n] = kcb[kk*NB + n0 + n];
            vcs[kk][n] = vcb[kk*NB + n0 + n];
        }
        __syncthreads();

        int lim = (tile == qtile) ? ((tid + 1) >> 2) : 64;

        for (int n4 = 0; n4 < 64; n4 += 4) {
            if (n4 >= lim) break;
            float s0 = 0.f, s1 = 0.f, s2 = 0.f, s3 = 0.f;
            #pragma unroll
            for (int kk = 0; kk < 32; kk++) {
                float4 kf = *(const float4*)&kcs[kk][n4];
                s0 = fmaf(qv[kk], kf.x, s0);
                s1 = fmaf(qv[kk], kf.y, s1);
                s2 = fmaf(qv[kk], kf.z, s2);
                s3 = fmaf(qv[kk], kf.w, s3);
            }
            // mask invisible n (only possible in partial tile)
            if (n4 + 1 >= lim) s1 = -INFINITY;
            if (n4 + 2 >= lim) s2 = -INFINITY;
            if (n4 + 3 >= lim) s3 = -INFINITY;

            int gn = n0 + n4;
            // top-1 non-own visible block (sequential -> lowest index on ties)
            if (gn + 0 != own && s0 > bval) { bval = s0; bidx = gn + 0; }
            if (gn + 1 != own && s1 > bval) { bval = s1; bidx = gn + 1; }
            if (gn + 2 != own && s2 > bval) { bval = s2; bidx = gn + 2; }
            if (gn + 3 != own && s3 > bval) { bval = s3; bidx = gn + 3; }

            float m4 = fmaxf(fmaxf(s0, s1), fmaxf(s2, s3));   // finite: s0 always valid here
            if (m4 > Ml) {
                float r = __expf(Ml - m4);   // 0 on first valid group
                Z *= r;
                #pragma unroll
                for (int j = 0; j < 32; j++) av[j] *= r;
                Ml = m4;
            }
            float p0 = __expf(s0 - Ml);
            float p1 = __expf(s1 - Ml);
            float p2 = __expf(s2 - Ml);
            float p3 = __expf(s3 - Ml);
            Z += (p0 + p1) + (p2 + p3);
            #pragma unroll
            for (int j = 0; j < 32; j++) {
                float4 vf = *(const float4*)&vcs[j][n4];
                av[j] = fmaf(p0, vf.x, av[j]);
                av[j] = fmaf(p1, vf.y, av[j]);
                av[j] = fmaf(p2, vf.z, av[j]);
                av[j] = fmaf(p3, vf.w, av[j]);
            }
        }
    }

    // fallback: no visible non-own block -> first non-own index (fully masked later)
    if (bval == -INFINITY) bidx = (own == 0) ? 1 : 0;

    // gates
    const float* gr = g + (size_t)(b*SS + t)*24;
    float g0 = gr[h], g1 = gr[8 + h], g2 = gr[16 + h];

    // res = g0 * compressed output
    float invZ = (Z > 0.f) ? (1.f / Z) : 0.f;
    float c0 = g0 * invZ;
    #pragma unroll
    for (int j = 0; j < 32; j++) av[j] *= c0;   // av now holds running result

    // ---- selection branch: blocks {own, bidx}, 8 keys, mask pos<=t ----
    float sc[8];
    float smax = -INFINITY;
    #pragma unroll
    for (int e = 0; e < 8; e++) {
        int pos = ((e < 4) ? own : bidx) * 4 + (e & 3);
        const float4* kr = (const float4*)(k + ((size_t)(b*SS + pos)*HH + h)*DHH);
        float s = 0.f;
        #pragma unroll
        for (int i = 0; i < 8; i++) {
            float4 kf = kr[i];
            s = fmaf(qv[4*i+0], kf.x, s);
            s = fmaf(qv[4*i+1], kf.y, s);
            s = fmaf(qv[4*i+2], kf.z, s);
            s = fmaf(qv[4*i+3], kf.w, s);
        }
        s = (pos <= t) ? s : -INFINITY;
        sc[e] = s;
        smax = fmaxf(smax, s);
    }
    float zf = 0.f;
    #pragma unroll
    for (int e = 0; e < 8; e++) { sc[e] = __expf(sc[e] - smax); zf += sc[e]; }
    float c1 = g1 / zf;
    #pragma unroll
    for (int e = 0; e < 8; e++) {
        int pos = ((e < 4) ? own : bidx) * 4 + (e & 3);
        float w = sc[e] * c1;
        const float4* vr = (const float4*)(v + ((size_t)(b*SS + pos)*HH + h)*DHH);
        #pragma unroll
        for (int i = 0; i < 8; i++) {
            float4 vf = vr[i];
            av[4*i+0] = fmaf(w, vf.x, av[4*i+0]);
            av[4*i+1] = fmaf(w, vf.y, av[4*i+1]);
            av[4*i+2] = fmaf(w, vf.z, av[4*i+2]);
            av[4*i+3] = fmaf(w, vf.w, av[4*i+3]);
        }
    }

    // ---- sliding-window branch: keys {t-1, t} ----
    int tp = (t > 0) ? t - 1 : 0;
    float s1w = 0.f, s0w = 0.f;
    {
        const float4* kr1 = (const float4*)(k + ((size_t)(b*SS + t )*HH + h)*DHH);
        const float4* kr0 = (const float4*)(k + ((size_t)(b*SS + tp)*HH + h)*DHH);
        #pragma unroll
        for (int i = 0; i < 8; i++) {
            float4 k1 = kr1[i], k0 = kr0[i];
            s1w = fmaf(qv[4*i+0], k1.x, s1w); s0w = fmaf(qv[4*i+0], k0.x, s0w);
            s1w = fmaf(qv[4*i+1], k1.y, s1w); s0w = fmaf(qv[4*i+1], k0.y, s0w);
            s1w = fmaf(qv[4*i+2], k1.z, s1w); s0w = fmaf(qv[4*i+2], k0.z, s0w);
            s1w = fmaf(qv[4*i+3], k1.w, s1w); s0w = fmaf(qv[4*i+3], k0.w, s0w);
        }
    }
    if (t == 0) s0w = -INFINITY;
    float wm = fmaxf(s0w, s1w);
    float p0w = __expf(s0w - wm), p1w = __expf(s1w - wm);
    float c2 = g2 / (p0w + p1w);
    float w0 = p0w * c2, w1 = p1w * c2;
    {
        const float4* vr1 = (const float4*)(v + ((size_t)(b*SS + t )*HH + h)*DHH);
        const float4* vr0 = (const float4*)(v + ((size_t)(b*SS + tp)*HH + h)*DHH);
        #pragma unroll
        for (int i = 0; i < 8; i++) {
            float4 v1 = vr1[i], v0 = vr0[i];
            av[4*i+0] = fmaf(w1, v1.x, fmaf(w0, v0.x, av[4*i+0]));
            av[4*i+1] = fmaf(w1, v1.y, fmaf(w0, v0.y, av[4*i+1]));
            av[4*i+2] = fmaf(w1, v1.z, fmaf(w0, v0.z, av[4*i+2]));
            av[4*i+3] = fmaf(w1, v1.w, fmaf(w0, v0.w, av[4*i+3]));
        }
    }

    // write out
    float4* orow = (float4*)(o + ((size_t)(b*SS + t)*HH + h)*DHH);
    #pragma unroll
    for (int i = 0; i < 8; i++) {
        float4 f;
        f.x = av[4*i+0]; f.y = av[4*i+1]; f.z = av[4*i+2]; f.w = av[4*i+3];
        orow[i] = f;
    }
}

// ---------------- host orchestration ----------------
extern "C" void kernel_launch(void* const* d_in, const int* in_sizes, int n_in,
                              void* d_out, int out_size)
{
    const float* x_in   = (const float*)d_in[0];
    const float* ln_a_g = (const float*)d_in[1];
    const float* ln_a_b = (const float*)d_in[2];
    const float* Wq     = (const float*)d_in[3];
    const float* Wk     = (const float*)d_in[4];
    const float* Wv     = (const float*)d_in[5];
    const float* Wg     = (const float*)d_in[6];
    const float* Wo     = (const float*)d_in[7];
    const float* ln_f_g = (const float*)d_in[8];
    const float* ln_f_b = (const float*)d_in[9];
    const float* W1     = (const float*)d_in[10];
    const float* b1     = (const float*)d_in[11];
    const float* W2     = (const float*)d_in[12];
    const float* b2     = (const float*)d_in[13];
    float* x = (float*)d_out;

    float *ph, *pq, *pk, *pv, *po, *pg, *pkc, *pvc, *pmid;
    cudaGetSymbolAddress((void**)&ph,   g_h);
    cudaGetSymbolAddress((void**)&pq,   g_q);
    cudaGetSymbolAddress((void**)&pk,   g_k);
    cudaGetSymbolAddress((void**)&pv,   g_v);
    cudaGetSymbolAddress((void**)&po,   g_o);
    cudaGetSymbolAddress((void**)&pg,   g_g);
    cudaGetSymbolAddress((void**)&pkc,  g_kc);
    cudaGetSymbolAddress((void**)&pvc,  g_vc);
    cudaGetSymbolAddress((void**)&pmid, g_mid);

    cudaMemcpyAsync(x, x_in, (size_t)BSD * sizeof(float), cudaMemcpyDeviceToDevice, 0);

    for (int l = 0; l < 2; l++) {
        for (int j2 = 0; j2 < 2; j2++) {
            int li = l*2 + j2;
            ln_kernel<<<BS/8, 256>>>(x, ln_a_g + li*DIMM, ln_a_b + li*DIMM, ph);
            gemm128_kernel<0><<<dim3(2, 64), 256>>>(ph, Wq + (size_t)li*DIMM*DIMM, nullptr, pq, BS, DIMM, DIMM);
            gemm128_kernel<0><<<dim3(2, 64), 256>>>(ph, Wk + (size_t)li*DIMM*DIMM, nullptr, pk, BS, DIMM, DIMM);
            gemm128_kernel<0><<<dim3(2, 64), 256>>>(ph, Wv + (size_t)li*DIMM*DIMM, nullptr, pv, BS, DIMM, DIMM);
            gemm_kernel<1><<<dim3(1, BS/64), 256>>>(ph, Wg + (size_t)li*DIMM*24, nullptr, pg, BS, 24, DIMM);
            pool_kernel<<<(BB*HH*NB*32)/256, 256>>>(pk, pv, pkc, pvc);
            nsa_attn_kernel<<<BB*HH*NQT, 256>>>(pq, pk, pv, pkc, pvc, pg, po);
            gemm128_kernel<4><<<dim3(2, 64), 256>>>(po, Wo + (size_t)li*DIMM*DIMM, nullptr, x, BS, DIMM, DIMM);
        }
        ln_kernel<<<BS/8, 256>>>(x, ln_f_g + l*DIMM, ln_f_b + l*DIMM, ph);
        gemm128_kernel<2><<<dim3(4, 64), 256>>>(ph,   W1 + (size_t)l*DIMM*512, b1 + l*512,  pmid, BS, 512,  DIMM);
        gemm128_kernel<3><<<dim3(2, 64), 256>>>(pmid, W2 + (size_t)l*512*DIMM, b2 + l*DIMM, x,    BS, DIMM, 512);
    }
}